// round 1
// baseline (speedup 1.0000x reference)
#include <cuda_runtime.h>

// Problem shape (fixed for this problem instance)
#define B_   32
#define C_   64
#define H_   64
#define W_   64
#define K_   512
#define HW_  (H_ * W_)          // 4096
#define NPIX (B_ * HW_)         // 131072 pixels
#define NE   (B_ * C_ * HW_)    // 8388608 elements of z_e / z_q
#define TPB  256
#define NBLK (NPIX / TPB)       // 512 blocks

// Per-block loss partials (scratch; rewritten fully every launch -> deterministic)
__device__ float g_partials[NBLK];

// ---- packed f32x2 helpers (sm_100+ packed-FP32 pipe; 2x FFMA throughput) ----
__device__ __forceinline__ unsigned long long fma2(unsigned long long a,
                                                   unsigned long long b,
                                                   unsigned long long c) {
    unsigned long long d;
    asm("fma.rn.f32x2 %0, %1, %2, %3;" : "=l"(d) : "l"(a), "l"(b), "l"(c));
    return d;
}
__device__ __forceinline__ unsigned long long add2(unsigned long long a,
                                                   unsigned long long b) {
    unsigned long long d;
    asm("add.rn.f32x2 %0, %1, %2;" : "=l"(d) : "l"(a), "l"(b));
    return d;
}
__device__ __forceinline__ unsigned long long pack2(float x, float y) {
    unsigned long long u;
    asm("mov.b64 %0, {%1, %2};" : "=l"(u) : "f"(x), "f"(y));
    return u;
}
__device__ __forceinline__ float2 unpack2(unsigned long long u) {
    float2 f;
    asm("mov.b64 {%0, %1}, %2;" : "=f"(f.x), "=f"(f.y) : "l"(u));
    return f;
}

// Main kernel: per-pixel argmin over 512 codes, write z_q + index, per-block loss partial.
__global__ void __launch_bounds__(TPB, 1)
vq_main(const float* __restrict__ z, const float* __restrict__ cb,
        float* __restrict__ zq_out, float* __restrict__ idx_out) {
    extern __shared__ float sm[];
    float* cbs = sm;             // [K_ * C_]  codebook, row-major
    float* en  = sm + K_ * C_;   // [K_]       ||e_k||^2

    const int tid = threadIdx.x;

    // Stage codebook into SMEM (128 KB) via float4
    {
        float4* dst = (float4*)cbs;
        const float4* src = (const float4*)cb;
        #pragma unroll
        for (int i = tid; i < (K_ * C_) / 4; i += TPB) dst[i] = src[i];
    }
    __syncthreads();

    // ||e_k||^2 per code
    for (int k = tid; k < K_; k += TPB) {
        const float* cp = cbs + k * C_;
        float s = 0.f;
        #pragma unroll
        for (int c = 0; c < C_; ++c) s = fmaf(cp[c], cp[c], s);
        en[k] = s;
    }
    __syncthreads();

    // This thread's pixel
    const int p  = blockIdx.x * TPB + tid;
    const int b  = p >> 12;        // / 4096
    const int hw = p & 4095;
    const float* zp = z + (size_t)b * (C_ * HW_) + hw;

    // Load z vector (64 floats, stride HW_) into 32 packed f32x2 regs; compute ||z||^2
    unsigned long long zr[32];
    float znorm = 0.f;
    #pragma unroll
    for (int i = 0; i < 32; ++i) {
        float x = zp[(2 * i) * HW_];
        float y = zp[(2 * i + 1) * HW_];
        znorm = fmaf(x, x, znorm);
        znorm = fmaf(y, y, znorm);
        zr[i] = pack2(x, y);
    }

    // Argmin over codes: dist_k = (||z||^2 + ||e_k||^2) - 2 * dot(z, e_k)
    float best  = 3.402823466e38f;
    int   bestk = 0;
    #pragma unroll 1
    for (int k = 0; k < K_; ++k) {
        const ulonglong2* cp = (const ulonglong2*)(cbs + k * C_);  // 128-bit LDS, broadcast
        unsigned long long a0 = 0ull, a1 = 0ull, a2 = 0ull, a3 = 0ull;
        #pragma unroll
        for (int j = 0; j < 16; j += 2) {
            ulonglong2 v0 = cp[j];
            ulonglong2 v1 = cp[j + 1];
            a0 = fma2(zr[2 * j + 0], v0.x, a0);
            a1 = fma2(zr[2 * j + 1], v0.y, a1);
            a2 = fma2(zr[2 * j + 2], v1.x, a2);
            a3 = fma2(zr[2 * j + 3], v1.y, a3);
        }
        a0 = add2(a0, a1);
        a2 = add2(a2, a3);
        a0 = add2(a0, a2);
        float2 f = unpack2(a0);
        float dot  = f.x + f.y;
        float dist = (znorm + en[k]) - 2.0f * dot;  // matches reference rounding
        if (dist < best) { best = dist; bestk = k; }  // strict < => first-min (argmin semantics)
    }

    // Epilogue: z_q_st = z + (q - z) (reference rounding), per-pixel loss, index
    const float* cbv = cbs + bestk * C_;
    float* zo = zq_out + (size_t)b * (C_ * HW_) + hw;
    float lsum = 0.f;
    #pragma unroll
    for (int i = 0; i < 32; ++i) {
        float2 f = unpack2(zr[i]);
        float q0 = cbv[2 * i];
        float q1 = cbv[2 * i + 1];
        float d0 = q0 - f.x;
        float d1 = q1 - f.y;
        lsum = fmaf(d0, d0, lsum);
        lsum = fmaf(d1, d1, lsum);
        zo[(2 * i) * HW_]     = f.x + d0;
        zo[(2 * i + 1) * HW_] = f.y + d1;
    }
    idx_out[p] = (float)bestk;

    // Block-level loss reduction
    #pragma unroll
    for (int off = 16; off > 0; off >>= 1)
        lsum += __shfl_down_sync(0xFFFFFFFFu, lsum, off);
    __shared__ float red[TPB / 32];
    if ((tid & 31) == 0) red[tid >> 5] = lsum;
    __syncthreads();
    if (tid == 0) {
        float t = 0.f;
        #pragma unroll
        for (int w = 0; w < TPB / 32; ++w) t += red[w];
        g_partials[blockIdx.x] = t;
    }
}

// Finalize: reduce partials -> loss = q_loss + 0.25 * e_loss = 1.25 * mean(||z_q - z_e||^2)
__global__ void vq_finalize(float* __restrict__ loss_out) {
    __shared__ float s[256];
    const int tid = threadIdx.x;
    s[tid] = g_partials[tid] + g_partials[tid + 256];
    __syncthreads();
    for (int off = 128; off > 0; off >>= 1) {
        if (tid < off) s[tid] += s[tid + off];
        __syncthreads();
    }
    if (tid == 0) {
        float q = s[0] / (float)NE;     // q_loss == e_loss numerically
        loss_out[0] = q + 0.25f * q;
    }
}

extern "C" void kernel_launch(void* const* d_in, const int* in_sizes, int n_in,
                              void* d_out, int out_size) {
    const float* z  = (const float*)d_in[0];   // z_e  [32,64,64,64]
    const float* cb = (const float*)d_in[1];   // codebook [512,64]
    float* out  = (float*)d_out;
    float* zq   = out;               // [NE]
    float* idx  = out + NE;          // [NPIX]
    float* loss = out + NE + NPIX;   // [1]

    const int smem_bytes = (K_ * C_ + K_) * (int)sizeof(float);  // 133120
    cudaFuncSetAttribute(vq_main, cudaFuncAttributeMaxDynamicSharedMemorySize, smem_bytes);

    vq_main<<<NBLK, TPB, smem_bytes>>>(z, cb, zq, idx);
    vq_finalize<<<1, 256>>>(loss);
}

// round 2
// speedup vs baseline: 1.4064x; 1.4064x over previous
#include <cuda_runtime.h>

// Problem shape (fixed)
#define B_   32
#define C_   64
#define HW_  4096
#define K_   512
#define NPIX 131072          // B_*HW_
#define NE   8388608         // B_*C_*HW_
#define TPB  256
#define PPT  2               // pixels per thread
#define PIX_PER_BLK (TPB * PPT)   // 512
#define NBLK (NPIX / PIX_PER_BLK) // 256

// Scratch (rewritten fully every launch -> deterministic)
__device__ float g_partials[NBLK];
__device__ unsigned int g_count;   // zero-initialized; reset to 0 by last block each launch

// ---- packed f32x2 helpers ----
__device__ __forceinline__ unsigned long long fma2(unsigned long long a,
                                                   unsigned long long b,
                                                   unsigned long long c) {
    unsigned long long d;
    asm("fma.rn.f32x2 %0, %1, %2, %3;" : "=l"(d) : "l"(a), "l"(b), "l"(c));
    return d;
}
__device__ __forceinline__ unsigned long long add2(unsigned long long a,
                                                   unsigned long long b) {
    unsigned long long d;
    asm("add.rn.f32x2 %0, %1, %2;" : "=l"(d) : "l"(a), "l"(b));
    return d;
}
__device__ __forceinline__ unsigned long long pack2(float x, float y) {
    unsigned long long u;
    asm("mov.b64 %0, {%1, %2};" : "=l"(u) : "f"(x), "f"(y));
    return u;
}
__device__ __forceinline__ float2 unpack2(unsigned long long u) {
    float2 f;
    asm("mov.b64 {%0, %1}, %2;" : "=f"(f.x), "=f"(f.y) : "l"(u));
    return f;
}

__global__ void __launch_bounds__(TPB, 1)
vq_main(const float* __restrict__ z, const float* __restrict__ cb,
        float* __restrict__ zq_out, float* __restrict__ idx_out,
        float* __restrict__ loss_out) {
    extern __shared__ float sm[];
    float* cbs = sm;             // [K_ * C_] codebook
    float* en  = sm + K_ * C_;   // [K_] ||e_k||^2

    const int tid = threadIdx.x;

    // Stage codebook into SMEM (128 KB)
    {
        float4* dst = (float4*)cbs;
        const float4* src = (const float4*)cb;
        #pragma unroll
        for (int i = tid; i < (K_ * C_) / 4; i += TPB) dst[i] = src[i];
    }
    __syncthreads();

    // ||e_k||^2 (same arithmetic as the passing round-1 kernel)
    for (int k = tid; k < K_; k += TPB) {
        const float* cp = cbs + k * C_;
        float s = 0.f;
        #pragma unroll
        for (int c = 0; c < C_; ++c) s = fmaf(cp[c], cp[c], s);
        en[k] = s;
    }
    __syncthreads();

    // Two pixels per thread, 512 consecutive pixels per block (same batch b)
    const int p0  = blockIdx.x * PIX_PER_BLK + tid;
    const int p1  = p0 + TPB;
    const int b   = p0 >> 12;          // 512 | 4096 -> same b for p0,p1
    const int hw0 = p0 & 4095;
    const int hw1 = p1 & 4095;
    const float* zb  = z + (size_t)b * (C_ * HW_);
    const float* zp0 = zb + hw0;
    const float* zp1 = zb + hw1;

    // Load both z vectors into packed f32x2 regs; ||z||^2 per pixel
    unsigned long long za[32], zc[32];
    float zn0 = 0.f, zn1 = 0.f;
    #pragma unroll
    for (int i = 0; i < 32; ++i) {
        float x0 = zp0[(2 * i) * HW_];
        float y0 = zp0[(2 * i + 1) * HW_];
        float x1 = zp1[(2 * i) * HW_];
        float y1 = zp1[(2 * i + 1) * HW_];
        zn0 = fmaf(x0, x0, zn0); zn0 = fmaf(y0, y0, zn0);
        zn1 = fmaf(x1, x1, zn1); zn1 = fmaf(y1, y1, zn1);
        za[i] = pack2(x0, y0);
        zc[i] = pack2(x1, y1);
    }

    // Argmin over 512 codes. Accumulation pattern identical to round-1 (bitwise-stable).
    float best0 = 3.402823466e38f, best1 = 3.402823466e38f;
    int   bk0 = 0, bk1 = 0;
    #pragma unroll 1
    for (int k = 0; k < K_; ++k) {
        const ulonglong2* cp = (const ulonglong2*)(cbs + k * C_);
        unsigned long long a0 = 0ull, a1 = 0ull, a2 = 0ull, a3 = 0ull;
        unsigned long long c0 = 0ull, c1 = 0ull, c2 = 0ull, c3 = 0ull;
        #pragma unroll
        for (int j = 0; j < 16; j += 2) {
            ulonglong2 v0 = cp[j];
            ulonglong2 v1 = cp[j + 1];
            a0 = fma2(za[2 * j + 0], v0.x, a0);
            a1 = fma2(za[2 * j + 1], v0.y, a1);
            a2 = fma2(za[2 * j + 2], v1.x, a2);
            a3 = fma2(za[2 * j + 3], v1.y, a3);
            c0 = fma2(zc[2 * j + 0], v0.x, c0);
            c1 = fma2(zc[2 * j + 1], v0.y, c1);
            c2 = fma2(zc[2 * j + 2], v1.x, c2);
            c3 = fma2(zc[2 * j + 3], v1.y, c3);
        }
        a0 = add2(a0, a1); a2 = add2(a2, a3); a0 = add2(a0, a2);
        c0 = add2(c0, c1); c2 = add2(c2, c3); c0 = add2(c0, c2);
        float2 fa = unpack2(a0);
        float2 fc = unpack2(c0);
        float dot0 = fa.x + fa.y;
        float dot1 = fc.x + fc.y;
        float ek   = en[k];
        float d0 = (zn0 + ek) - 2.0f * dot0;
        float d1 = (zn1 + ek) - 2.0f * dot1;
        if (d0 < best0) { best0 = d0; bk0 = k; }   // strict < -> first-min
        if (d1 < best1) { best1 = d1; bk1 = k; }
    }

    // Epilogue: z_q_st = z + (q - z), per-pixel loss, index (same rounding as round-1)
    float lsum = 0.f;
    {
        const float* cbv = cbs + bk0 * C_;
        float* zo = zq_out + (size_t)b * (C_ * HW_) + hw0;
        #pragma unroll
        for (int i = 0; i < 32; ++i) {
            float2 f = unpack2(za[i]);
            float d0 = cbv[2 * i]     - f.x;
            float d1 = cbv[2 * i + 1] - f.y;
            lsum = fmaf(d0, d0, lsum);
            lsum = fmaf(d1, d1, lsum);
            zo[(2 * i) * HW_]     = f.x + d0;
            zo[(2 * i + 1) * HW_] = f.y + d1;
        }
        idx_out[p0] = (float)bk0;
    }
    {
        const float* cbv = cbs + bk1 * C_;
        float* zo = zq_out + (size_t)b * (C_ * HW_) + hw1;
        #pragma unroll
        for (int i = 0; i < 32; ++i) {
            float2 f = unpack2(zc[i]);
            float d0 = cbv[2 * i]     - f.x;
            float d1 = cbv[2 * i + 1] - f.y;
            lsum = fmaf(d0, d0, lsum);
            lsum = fmaf(d1, d1, lsum);
            zo[(2 * i) * HW_]     = f.x + d0;
            zo[(2 * i + 1) * HW_] = f.y + d1;
        }
        idx_out[p1] = (float)bk1;
    }

    // Block loss reduction
    #pragma unroll
    for (int off = 16; off > 0; off >>= 1)
        lsum += __shfl_down_sync(0xFFFFFFFFu, lsum, off);
    __shared__ float red[TPB / 32];
    __shared__ int is_last;
    if ((tid & 31) == 0) red[tid >> 5] = lsum;
    __syncthreads();
    if (tid == 0) {
        float t = 0.f;
        #pragma unroll
        for (int w = 0; w < TPB / 32; ++w) t += red[w];
        g_partials[blockIdx.x] = t;
        __threadfence();
        unsigned int old = atomicAdd(&g_count, 1u);
        is_last = (old == NBLK - 1) ? 1 : 0;
    }
    __syncthreads();

    // Last block: reduce partials -> loss = 1.25 * mean(||z_q - z_e||^2)
    if (is_last) {
        __shared__ float s[TPB];
        float v;
        asm volatile("ld.global.cg.f32 %0, [%1];" : "=f"(v) : "l"(g_partials + tid));
        s[tid] = v;
        __syncthreads();
        for (int off = TPB / 2; off > 0; off >>= 1) {
            if (tid < off) s[tid] += s[tid + off];
            __syncthreads();
        }
        if (tid == 0) {
            float q = s[0] / (float)NE;   // q_loss == e_loss numerically
            loss_out[0] = q + 0.25f * q;
            g_count = 0;                  // reset for next (graph) replay
        }
    }
}

extern "C" void kernel_launch(void* const* d_in, const int* in_sizes, int n_in,
                              void* d_out, int out_size) {
    const float* z  = (const float*)d_in[0];   // z_e [32,64,64,64] f32
    const float* cb = (const float*)d_in[1];   // codebook [512,64] f32
    float* out  = (float*)d_out;
    float* zq   = out;               // [NE]
    float* idx  = out + NE;          // [NPIX]
    float* loss = out + NE + NPIX;   // [1]

    const int smem_bytes = (K_ * C_ + K_) * (int)sizeof(float);  // 133120
    cudaFuncSetAttribute(vq_main, cudaFuncAttributeMaxDynamicSharedMemorySize, smem_bytes);
    vq_main<<<NBLK, TPB, smem_bytes>>>(z, cb, zq, idx, loss);
}